// round 6
// baseline (speedup 1.0000x reference)
#include <cuda_runtime.h>

#define NN   50000
#define NE   800000
#define FIN  96
#define FH   64
#define FOUT 40
#define N1   128   // FH*2  (cols 0-63: W1_0 path, 64-127: W1_1 path)
#define N2   80    // FOUT*2
#define SCAN_B 1024
#define NBLK_SCAN ((NN + SCAN_B - 1) / SCAN_B)   // 49

// Scratch (device globals: no allocations allowed)
__device__ __align__(16) float g_C1[NN * N1];   // [h_pre | y1]
__device__ __align__(16) float g_H[NN * FH];    // relu(h_pre + A_norm y1)
__device__ __align__(16) float g_y2[NN * FOUT]; // h @ W2_1
__device__ float g_dis[NN];                     // deg^{-1/2}
__device__ int   g_deg[NN];
__device__ int   g_off[NN];                     // CSR row offsets
__device__ int   g_cur[NN];                     // bucket cursors
__device__ int   g_bsum[NBLK_SCAN];
__device__ int   g_col[NE];                     // CSR col indices
__device__ float g_w[NE];                       // CSR edge weights
__device__ int   g_is64;                        // 1 if edge_index is int64, 0 if int32

__device__ __forceinline__ int edge_at(const void* ei, int which, int e) {
    if (g_is64) return (int)((const long long*)ei)[(size_t)which * NE + e];
    return ((const int*)ei)[(size_t)which * NE + e];
}

// ---------------- init (zero counters) + parallel dtype detect ----------------
__global__ void k_zero(const void* ei) {
    int i = blockIdx.x * blockDim.x + threadIdx.x;
    if (i < NN) { g_deg[i] = 0; g_cur[i] = 0; }
    if (blockIdx.x == 0 && threadIdx.x < 32) {
        const unsigned long long* p = (const unsigned long long*)ei;
        unsigned long long v0 = p[threadIdx.x];
        unsigned long long v1 = p[32 + threadIdx.x];
        int bad = (v0 >= (unsigned long long)NN) || (v1 >= (unsigned long long)NN);
        unsigned m = __ballot_sync(0xffffffffu, bad);
        if (threadIdx.x == 0) g_is64 = (m == 0u) ? 1 : 0;
    }
}

__global__ void k_deg(const void* __restrict__ ei) {
    int e = blockIdx.x * blockDim.x + threadIdx.x;
    if (e < NE) {
        int r = edge_at(ei, 0, e);
        if ((unsigned)r < NN) atomicAdd(&g_deg[r], 1);
    }
}

// ---------------- scanA (+ dis fused) ----------------
__global__ __launch_bounds__(SCAN_B) void k_scanA() {
    __shared__ int s[SCAN_B];
    int i = blockIdx.x * SCAN_B + threadIdx.x;
    int v = (i < NN) ? g_deg[i] : 0;
    if (i < NN) g_dis[i] = (v > 0) ? rsqrtf((float)v) : 0.f;
    s[threadIdx.x] = v;
    __syncthreads();
#pragma unroll
    for (int off = 1; off < SCAN_B; off <<= 1) {
        int t = (threadIdx.x >= off) ? s[threadIdx.x - off] : 0;
        __syncthreads();
        s[threadIdx.x] += t;
        __syncthreads();
    }
    if (i < NN) g_off[i] = s[threadIdx.x] - v;   // exclusive
    if (threadIdx.x == SCAN_B - 1) g_bsum[blockIdx.x] = s[SCAN_B - 1];
}

__global__ void k_scanB() {
    int lane = threadIdx.x;
    int v0 = (lane < NBLK_SCAN) ? g_bsum[lane] : 0;
    int v1 = (32 + lane < NBLK_SCAN) ? g_bsum[32 + lane] : 0;
    int s0 = v0;
#pragma unroll
    for (int o = 1; o < 32; o <<= 1) {
        int t = __shfl_up_sync(0xffffffffu, s0, o);
        if (lane >= o) s0 += t;
    }
    int tot0 = __shfl_sync(0xffffffffu, s0, 31);
    int s1 = v1;
#pragma unroll
    for (int o = 1; o < 32; o <<= 1) {
        int t = __shfl_up_sync(0xffffffffu, s1, o);
        if (lane >= o) s1 += t;
    }
    if (lane < NBLK_SCAN) g_bsum[lane] = s0 - v0;
    if (32 + lane < NBLK_SCAN) g_bsum[32 + lane] = tot0 + s1 - v1;
}

__global__ void k_scanC() {
    int i = blockIdx.x * blockDim.x + threadIdx.x;
    if (i < NN) g_off[i] += g_bsum[i / SCAN_B];
}

// ---------------- bucket edges into CSR ----------------
__global__ void k_bucket(const void* __restrict__ ei) {
    int e = blockIdx.x * blockDim.x + threadIdx.x;
    if (e >= NE) return;
    int r = edge_at(ei, 0, e);
    int c = edge_at(ei, 1, e);
    if ((unsigned)r >= NN || (unsigned)c >= NN) return;
    int slot = g_off[r] + atomicAdd(&g_cur[r], 1);
    g_col[slot] = c;
    g_w[slot]   = -g_dis[r] * g_dis[c];
}

// ---------------- GEMM1: C1[NN x 128] = x[NN x 96] @ [W1_0 | W1_1], +b1 on cols<64 ----
__global__ __launch_bounds__(256) void k_gemm1(const float* __restrict__ x,
                                               const float* __restrict__ W0,
                                               const float* __restrict__ W1,
                                               const float* __restrict__ b1) {
    __shared__ float ws[32][N1];   // 16 KB
    __shared__ float xs[64][32];   // 8 KB
    const int t  = threadIdx.x;
    const int cg = t & 31;
    const int rg = t >> 5;
    const int r0 = blockIdx.x * 64;

    float acc[8][4];
#pragma unroll
    for (int i = 0; i < 8; i++)
#pragma unroll
        for (int j = 0; j < 4; j++) acc[i][j] = 0.f;

    for (int kc = 0; kc < FIN; kc += 32) {
        for (int idx = t; idx < 32 * FH; idx += 256) {
            int kk = idx >> 6;
            int j  = idx & 63;
            int gk = kc + kk;
            ws[kk][j]      = W0[gk * FH + j];
            ws[kk][64 + j] = W1[gk * FH + j];
        }
        for (int idx = t; idx < 512; idx += 256) {
            int r  = idx >> 3;
            int c4 = idx & 7;
            int row = r0 + r;
            float4 v = make_float4(0.f, 0.f, 0.f, 0.f);
            if (row < NN) v = *(const float4*)&x[row * FIN + kc + c4 * 4];
            *(float4*)&xs[r][c4 * 4] = v;
        }
        __syncthreads();
#pragma unroll 8
        for (int k = 0; k < 32; k++) {
            float4 w = *(const float4*)&ws[k][cg * 4];
#pragma unroll
            for (int i = 0; i < 8; i++) {
                float a = xs[rg * 8 + i][k];
                acc[i][0] += a * w.x; acc[i][1] += a * w.y;
                acc[i][2] += a * w.z; acc[i][3] += a * w.w;
            }
        }
        __syncthreads();
    }

    const int col = cg * 4;
    float4 bb = make_float4(0.f, 0.f, 0.f, 0.f);
    if (col < FH) bb = *(const float4*)&b1[col];
#pragma unroll
    for (int i = 0; i < 8; i++) {
        int row = r0 + rg * 8 + i;
        if (row < NN) {
            float4 v = make_float4(acc[i][0] + bb.x, acc[i][1] + bb.y,
                                   acc[i][2] + bb.z, acc[i][3] + bb.w);
            *(float4*)&g_C1[row * N1 + col] = v;
        }
    }
}

// ---------------- SpMM1 (pull, warp/node, float2 + 4x unroll) ------------------------
__global__ __launch_bounds__(256) void k_spmm1() {
    const int wid  = threadIdx.x >> 5;
    const int lane = threadIdx.x & 31;
    const int r = blockIdx.x * 8 + wid;
    if (r >= NN) return;

    const int e0 = g_off[r];
    const int d  = g_cur[r];
    float2 a0 = {0.f, 0.f}, a1 = {0.f, 0.f}, a2 = {0.f, 0.f}, a3 = {0.f, 0.f};
    const float2* __restrict__ C2 = (const float2*)g_C1;   // row c: c*64 float2

    for (int base = 0; base < d; base += 32) {
        int   cl = 0;  float wl = 0.f;
        int   j  = base + lane;
        if (j < d) { cl = g_col[e0 + j]; wl = g_w[e0 + j]; }
        const int lim = min(32, d - base);
        int jj = 0;
        for (; jj + 4 <= lim; jj += 4) {
            int   c0 = __shfl_sync(0xffffffffu, cl, jj);
            int   c1 = __shfl_sync(0xffffffffu, cl, jj + 1);
            int   c2 = __shfl_sync(0xffffffffu, cl, jj + 2);
            int   c3 = __shfl_sync(0xffffffffu, cl, jj + 3);
            float w0 = __shfl_sync(0xffffffffu, wl, jj);
            float w1 = __shfl_sync(0xffffffffu, wl, jj + 1);
            float w2 = __shfl_sync(0xffffffffu, wl, jj + 2);
            float w3 = __shfl_sync(0xffffffffu, wl, jj + 3);
            float2 v0 = __ldg(&C2[c0 * 64 + 32 + lane]);
            float2 v1 = __ldg(&C2[c1 * 64 + 32 + lane]);
            float2 v2 = __ldg(&C2[c2 * 64 + 32 + lane]);
            float2 v3 = __ldg(&C2[c3 * 64 + 32 + lane]);
            a0.x += w0 * v0.x; a0.y += w0 * v0.y;
            a1.x += w1 * v1.x; a1.y += w1 * v1.y;
            a2.x += w2 * v2.x; a2.y += w2 * v2.y;
            a3.x += w3 * v3.x; a3.y += w3 * v3.y;
        }
        for (; jj < lim; jj++) {
            int   c = __shfl_sync(0xffffffffu, cl, jj);
            float w = __shfl_sync(0xffffffffu, wl, jj);
            float2 v = __ldg(&C2[c * 64 + 32 + lane]);
            a0.x += w * v.x; a0.y += w * v.y;
        }
    }
    float2 acc = make_float2(a0.x + a1.x + a2.x + a3.x,
                             a0.y + a1.y + a2.y + a3.y);
    float2 pre = C2[r * 64 + lane];
    float2 hv = make_float2(fmaxf(pre.x + acc.x, 0.f), fmaxf(pre.y + acc.y, 0.f));
    ((float2*)g_H)[r * 32 + lane] = hv;
}

// ---------------- GEMM2: out_pre = H@W2_0 + b2 -> d_out ; y2 = H@W2_1 ----------------
__global__ __launch_bounds__(320) void k_gemm2(const float* __restrict__ W20,
                                               const float* __restrict__ W21,
                                               const float* __restrict__ b2,
                                               float* __restrict__ out) {
    __shared__ float hs[64][FH];   // 16 KB
    __shared__ float ws[FH][N2];   // 20 KB
    const int t  = threadIdx.x;    // 320
    const int r0 = blockIdx.x * 64;

    for (int idx = t; idx < FH * N2; idx += 320) {
        int k = idx / N2;
        int j = idx % N2;
        ws[k][j] = (j < FOUT) ? W20[k * FOUT + j] : W21[k * FOUT + (j - FOUT)];
    }
    for (int idx = t; idx < 64 * FH; idx += 320) {
        int r = idx >> 6;
        int k = idx & 63;
        int row = r0 + r;
        hs[r][k] = (row < NN) ? g_H[row * FH + k] : 0.f;
    }
    __syncthreads();

    const int cg = t % 20;
    const int rg = t / 20;
    float acc[4][4];
#pragma unroll
    for (int i = 0; i < 4; i++)
#pragma unroll
        for (int j = 0; j < 4; j++) acc[i][j] = 0.f;

#pragma unroll 4
    for (int k = 0; k < FH; k++) {
        float4 w = *(const float4*)&ws[k][cg * 4];
#pragma unroll
        for (int i = 0; i < 4; i++) {
            float a = hs[rg * 4 + i][k];
            acc[i][0] += a * w.x; acc[i][1] += a * w.y;
            acc[i][2] += a * w.z; acc[i][3] += a * w.w;
        }
    }

    const int col = cg * 4;
#pragma unroll
    for (int i = 0; i < 4; i++) {
        int row = r0 + rg * 4 + i;
        if (row >= NN) continue;
        if (col < FOUT) {
            float4 bb = *(const float4*)&b2[col];
            float4 v = make_float4(acc[i][0] + bb.x, acc[i][1] + bb.y,
                                   acc[i][2] + bb.z, acc[i][3] + bb.w);
            *(float4*)&out[row * FOUT + col] = v;
        } else {
            float4 v = make_float4(acc[i][0], acc[i][1], acc[i][2], acc[i][3]);
            *(float4*)&g_y2[row * FOUT + (col - FOUT)] = v;
        }
    }
}

// ---------------- SpMM2 (pull, warp/node, float2 + 4x unroll): out[r] += sum w*y2[c] --
__global__ __launch_bounds__(256) void k_spmm2(float* __restrict__ out) {
    const int wid  = threadIdx.x >> 5;
    const int lane = threadIdx.x & 31;
    const int r = blockIdx.x * 8 + wid;
    if (r >= NN) return;

    const int e0 = g_off[r];
    const int d  = g_cur[r];
    const bool act = lane < 20;                 // 20 float2 = 40 feats
    float2 a0 = {0.f, 0.f}, a1 = {0.f, 0.f}, a2 = {0.f, 0.f}, a3 = {0.f, 0.f};
    const float2* __restrict__ Y2 = (const float2*)g_y2;  // row c: c*20 float2

    for (int base = 0; base < d; base += 32) {
        int   cl = 0;  float wl = 0.f;
        int   j  = base + lane;
        if (j < d) { cl = g_col[e0 + j]; wl = g_w[e0 + j]; }
        const int lim = min(32, d - base);
        int jj = 0;
        for (; jj + 4 <= lim; jj += 4) {
            int   c0 = __shfl_sync(0xffffffffu, cl, jj);
            int   c1 = __shfl_sync(0xffffffffu, cl, jj + 1);
            int   c2 = __shfl_sync(0xffffffffu, cl, jj + 2);
            int   c3 = __shfl_sync(0xffffffffu, cl, jj + 3);
            float w0 = __shfl_sync(0xffffffffu, wl, jj);
            float w1 = __shfl_sync(0xffffffffu, wl, jj + 1);
            float w2 = __shfl_sync(0xffffffffu, wl, jj + 2);
            float w3 = __shfl_sync(0xffffffffu, wl, jj + 3);
            if (act) {
                float2 v0 = __ldg(&Y2[c0 * 20 + lane]);
                float2 v1 = __ldg(&Y2[c1 * 20 + lane]);
                float2 v2 = __ldg(&Y2[c2 * 20 + lane]);
                float2 v3 = __ldg(&Y2[c3 * 20 + lane]);
                a0.x += w0 * v0.x; a0.y += w0 * v0.y;
                a1.x += w1 * v1.x; a1.y += w1 * v1.y;
                a2.x += w2 * v2.x; a2.y += w2 * v2.y;
                a3.x += w3 * v3.x; a3.y += w3 * v3.y;
            }
        }
        for (; jj < lim; jj++) {
            int   c = __shfl_sync(0xffffffffu, cl, jj);
            float w = __shfl_sync(0xffffffffu, wl, jj);
            if (act) {
                float2 v = __ldg(&Y2[c * 20 + lane]);
                a0.x += w * v.x; a0.y += w * v.y;
            }
        }
    }
    if (act) {
        float2 acc = make_float2(a0.x + a1.x + a2.x + a3.x,
                                 a0.y + a1.y + a2.y + a3.y);
        float2* o = &((float2*)out)[r * 20 + lane];
        float2 cur = *o;
        cur.x += acc.x; cur.y += acc.y;
        *o = cur;
    }
}

extern "C" void kernel_launch(void* const* d_in, const int* in_sizes, int n_in,
                              void* d_out, int out_size) {
    const float* x   = (const float*)d_in[0];
    const void*  ei  = d_in[1];
    const float* W10 = (const float*)d_in[2];
    const float* W11 = (const float*)d_in[3];
    const float* b1  = (const float*)d_in[4];
    const float* W20 = (const float*)d_in[5];
    const float* W21 = (const float*)d_in[6];
    const float* b2  = (const float*)d_in[7];
    float* out = (float*)d_out;

    k_zero  <<<(NN + 255) / 256, 256>>>(ei);
    k_deg   <<<(NE + 255) / 256, 256>>>(ei);
    k_scanA <<<NBLK_SCAN, SCAN_B>>>();
    k_scanB <<<1, 32>>>();
    k_scanC <<<(NN + 255) / 256, 256>>>();
    k_bucket<<<(NE + 255) / 256, 256>>>(ei);
    k_gemm1 <<<(NN + 63) / 64, 256>>>(x, W10, W11, b1);
    k_spmm1 <<<(NN + 7) / 8, 256>>>();
    k_gemm2 <<<(NN + 63) / 64, 320>>>(W20, W21, b2, out);
    k_spmm2 <<<(NN + 7) / 8, 256>>>(out);
}

// round 8
// speedup vs baseline: 1.1061x; 1.1061x over previous
#include <cuda_runtime.h>
#include <cstdint>

#define NN   50000
#define NE   800000
#define FIN  96
#define FH   64
#define FOUT 40
#define N1   128   // FH*2
#define N2   80    // FOUT*2
#define SCAN_B 1024
#define NBLK_SCAN ((NN + SCAN_B - 1) / SCAN_B)   // 49

__device__ __align__(16) float g_C1[NN * N1];   // [h_pre | y1]
__device__ __align__(16) float g_H[NN * FH];    // relu(h_pre + A_norm y1)
__device__ __align__(16) float g_y2[NN * FOUT]; // h @ W2_1
__device__ float g_dis[NN];
__device__ int   g_deg[NN];
__device__ int   g_off[NN];
__device__ int   g_cur[NN];
__device__ int   g_bsum[NBLK_SCAN];
__device__ int   g_col[NE];
__device__ float g_w[NE];
__device__ int   g_is64;

__device__ __forceinline__ int edge_at(const void* ei, int which, int e) {
    if (g_is64) return (int)((const long long*)ei)[(size_t)which * NE + e];
    return ((const int*)ei)[(size_t)which * NE + e];
}

// tf32 conversion: destination must be a b32 register (bit pattern of tf32 value)
__device__ __forceinline__ float to_tf32(float x) {
    uint32_t y;
    asm("cvt.rna.tf32.f32 %0, %1;" : "=r"(y) : "f"(x));
    return __uint_as_float(y);
}

__device__ __forceinline__ void mma_tf32(float c[4], const uint32_t a[4], const uint32_t b[2]) {
    asm volatile(
        "mma.sync.aligned.m16n8k8.row.col.f32.tf32.tf32.f32 "
        "{%0,%1,%2,%3}, {%4,%5,%6,%7}, {%8,%9}, {%0,%1,%2,%3};"
        : "+f"(c[0]), "+f"(c[1]), "+f"(c[2]), "+f"(c[3])
        : "r"(a[0]), "r"(a[1]), "r"(a[2]), "r"(a[3]), "r"(b[0]), "r"(b[1]));
}

// ---------------- init (zero counters) + parallel dtype detect ----------------
__global__ void k_zero(const void* ei) {
    int i = blockIdx.x * blockDim.x + threadIdx.x;
    if (i < NN) { g_deg[i] = 0; g_cur[i] = 0; }
    if (blockIdx.x == 0 && threadIdx.x < 32) {
        const unsigned long long* p = (const unsigned long long*)ei;
        unsigned long long v0 = p[threadIdx.x];
        unsigned long long v1 = p[32 + threadIdx.x];
        int bad = (v0 >= (unsigned long long)NN) || (v1 >= (unsigned long long)NN);
        unsigned m = __ballot_sync(0xffffffffu, bad);
        if (threadIdx.x == 0) g_is64 = (m == 0u) ? 1 : 0;
    }
}

__global__ void k_deg(const void* __restrict__ ei) {
    int e = blockIdx.x * blockDim.x + threadIdx.x;
    if (e < NE) {
        int r = edge_at(ei, 0, e);
        if ((unsigned)r < NN) atomicAdd(&g_deg[r], 1);
    }
}

// ---------------- scanA (+ dis fused) ----------------
__global__ __launch_bounds__(SCAN_B) void k_scanA() {
    __shared__ int s[SCAN_B];
    int i = blockIdx.x * SCAN_B + threadIdx.x;
    int v = (i < NN) ? g_deg[i] : 0;
    if (i < NN) g_dis[i] = (v > 0) ? rsqrtf((float)v) : 0.f;
    s[threadIdx.x] = v;
    __syncthreads();
#pragma unroll
    for (int off = 1; off < SCAN_B; off <<= 1) {
        int t = (threadIdx.x >= off) ? s[threadIdx.x - off] : 0;
        __syncthreads();
        s[threadIdx.x] += t;
        __syncthreads();
    }
    if (i < NN) g_off[i] = s[threadIdx.x] - v;   // exclusive within block
    if (threadIdx.x == SCAN_B - 1) g_bsum[blockIdx.x] = s[SCAN_B - 1];
}

// scanC: add prefix of earlier block totals (per-block warp reduction, no scanB kernel)
__global__ __launch_bounds__(SCAN_B) void k_scanC() {
    __shared__ int sbase;
    const int bid = blockIdx.x;
    if (threadIdx.x < 32) {
        int lane = threadIdx.x;
        int v = (lane < bid) ? g_bsum[lane] : 0;
        if (32 + lane < bid) v += g_bsum[32 + lane];
#pragma unroll
        for (int o = 16; o > 0; o >>= 1) v += __shfl_down_sync(0xffffffffu, v, o);
        if (lane == 0) sbase = v;
    }
    __syncthreads();
    int i = bid * SCAN_B + threadIdx.x;
    if (i < NN) g_off[i] += sbase;
}

// ---------------- bucket edges into CSR ----------------
__global__ void k_bucket(const void* __restrict__ ei) {
    int e = blockIdx.x * blockDim.x + threadIdx.x;
    if (e >= NE) return;
    int r = edge_at(ei, 0, e);
    int c = edge_at(ei, 1, e);
    if ((unsigned)r >= NN || (unsigned)c >= NN) return;
    int slot = g_off[r] + atomicAdd(&g_cur[r], 1);
    g_col[slot] = c;
    g_w[slot]   = -g_dis[r] * g_dis[c];
}

// ---------------- GEMM1 (tf32 tensor cores): C1 = x @ [W1_0|W1_1] (+b1 on cols<64) ----
// CTA: 256 thr = 8 warps (2x4). CTA tile 64x128, warp tile 32x32, K-chunk 32.
__global__ __launch_bounds__(256) void k_gemm1(const float* __restrict__ x,
                                               const float* __restrict__ W0,
                                               const float* __restrict__ W1,
                                               const float* __restrict__ b1) {
    __shared__ float xs[64][36];    // stride 36: conflict-free A-frag loads
    __shared__ float ws[32][136];   // stride 136 (mod32==8): conflict-free B-frag loads
    const int t    = threadIdx.x;
    const int lane = t & 31;
    const int w    = t >> 5;
    const int wr   = w >> 2;        // 0..1
    const int wc   = w & 3;         // 0..3
    const int r0   = blockIdx.x * 64;

    float acc[2][4][4];
#pragma unroll
    for (int mb = 0; mb < 2; mb++)
#pragma unroll
        for (int nb = 0; nb < 4; nb++)
#pragma unroll
            for (int q = 0; q < 4; q++) acc[mb][nb][q] = 0.f;

    for (int kc = 0; kc < FIN; kc += 32) {
        // x tile: 64 rows x 32 cols (tf32-rounded)
        for (int idx = t; idx < 512; idx += 256) {
            int r  = idx >> 3;
            int c4 = idx & 7;
            int row = r0 + r;
            float4 v = make_float4(0.f, 0.f, 0.f, 0.f);
            if (row < NN) v = *(const float4*)&x[row * FIN + kc + c4 * 4];
            xs[r][c4 * 4 + 0] = to_tf32(v.x);
            xs[r][c4 * 4 + 1] = to_tf32(v.y);
            xs[r][c4 * 4 + 2] = to_tf32(v.z);
            xs[r][c4 * 4 + 3] = to_tf32(v.w);
        }
        // W tile: 32 k x 128 cols (W0 | W1), tf32-rounded
        for (int idx = t; idx < 32 * FH; idx += 256) {
            int kk = idx >> 6;
            int j  = idx & 63;
            int gk = kc + kk;
            ws[kk][j]      = to_tf32(W0[gk * FH + j]);
            ws[kk][64 + j] = to_tf32(W1[gk * FH + j]);
        }
        __syncthreads();

#pragma unroll
        for (int kk = 0; kk < 32; kk += 8) {
            uint32_t a[2][4];
            const int ar = lane >> 2;       // 0..7
            const int ak = kk + (lane & 3); // k
#pragma unroll
            for (int mb = 0; mb < 2; mb++) {
                int rr = wr * 32 + mb * 16 + ar;
                a[mb][0] = __float_as_uint(xs[rr][ak]);
                a[mb][1] = __float_as_uint(xs[rr + 8][ak]);
                a[mb][2] = __float_as_uint(xs[rr][ak + 4]);
                a[mb][3] = __float_as_uint(xs[rr + 8][ak + 4]);
            }
#pragma unroll
            for (int nb = 0; nb < 4; nb++) {
                uint32_t b[2];
                int col = wc * 32 + nb * 8 + (lane >> 2);
                b[0] = __float_as_uint(ws[ak][col]);
                b[1] = __float_as_uint(ws[ak + 4][col]);
                mma_tf32(acc[0][nb], a[0], b);
                mma_tf32(acc[1][nb], a[1], b);
            }
        }
        __syncthreads();
    }

    // epilogue: c0,c1 -> (row, col..col+1); c2,c3 -> (row+8, col..col+1)
#pragma unroll
    for (int mb = 0; mb < 2; mb++) {
#pragma unroll
        for (int nb = 0; nb < 4; nb++) {
            int row = r0 + wr * 32 + mb * 16 + (lane >> 2);
            int col = wc * 32 + nb * 8 + (lane & 3) * 2;
            float bx = 0.f, by = 0.f;
            if (col < FH) { bx = b1[col]; by = b1[col + 1]; }
            if (row < NN) {
                float2 v0 = make_float2(acc[mb][nb][0] + bx, acc[mb][nb][1] + by);
                *(float2*)&g_C1[row * N1 + col] = v0;
            }
            if (row + 8 < NN) {
                float2 v1 = make_float2(acc[mb][nb][2] + bx, acc[mb][nb][3] + by);
                *(float2*)&g_C1[(row + 8) * N1 + col] = v1;
            }
        }
    }
}

// ---------------- SpMM1 (pull, warp/node, float2 + 4x unroll) ------------------------
__global__ __launch_bounds__(256) void k_spmm1() {
    const int wid  = threadIdx.x >> 5;
    const int lane = threadIdx.x & 31;
    const int r = blockIdx.x * 8 + wid;
    if (r >= NN) return;

    const int e0 = g_off[r];
    const int d  = g_cur[r];
    float2 a0 = {0.f, 0.f}, a1 = {0.f, 0.f}, a2 = {0.f, 0.f}, a3 = {0.f, 0.f};
    const float2* __restrict__ C2 = (const float2*)g_C1;

    for (int base = 0; base < d; base += 32) {
        int   cl = 0;  float wl = 0.f;
        int   j  = base + lane;
        if (j < d) { cl = g_col[e0 + j]; wl = g_w[e0 + j]; }
        const int lim = min(32, d - base);
        int jj = 0;
        for (; jj + 4 <= lim; jj += 4) {
            int   c0 = __shfl_sync(0xffffffffu, cl, jj);
            int   c1 = __shfl_sync(0xffffffffu, cl, jj + 1);
            int   c2 = __shfl_sync(0xffffffffu, cl, jj + 2);
            int   c3 = __shfl_sync(0xffffffffu, cl, jj + 3);
            float w0 = __shfl_sync(0xffffffffu, wl, jj);
            float w1 = __shfl_sync(0xffffffffu, wl, jj + 1);
            float w2 = __shfl_sync(0xffffffffu, wl, jj + 2);
            float w3 = __shfl_sync(0xffffffffu, wl, jj + 3);
            float2 v0 = __ldg(&C2[c0 * 64 + 32 + lane]);
            float2 v1 = __ldg(&C2[c1 * 64 + 32 + lane]);
            float2 v2 = __ldg(&C2[c2 * 64 + 32 + lane]);
            float2 v3 = __ldg(&C2[c3 * 64 + 32 + lane]);
            a0.x += w0 * v0.x; a0.y += w0 * v0.y;
            a1.x += w1 * v1.x; a1.y += w1 * v1.y;
            a2.x += w2 * v2.x; a2.y += w2 * v2.y;
            a3.x += w3 * v3.x; a3.y += w3 * v3.y;
        }
        for (; jj < lim; jj++) {
            int   c = __shfl_sync(0xffffffffu, cl, jj);
            float w = __shfl_sync(0xffffffffu, wl, jj);
            float2 v = __ldg(&C2[c * 64 + 32 + lane]);
            a0.x += w * v.x; a0.y += w * v.y;
        }
    }
    float2 acc = make_float2(a0.x + a1.x + a2.x + a3.x,
                             a0.y + a1.y + a2.y + a3.y);
    float2 pre = C2[r * 64 + lane];
    float2 hv = make_float2(fmaxf(pre.x + acc.x, 0.f), fmaxf(pre.y + acc.y, 0.f));
    ((float2*)g_H)[r * 32 + lane] = hv;
}

// ---------------- GEMM2: out_pre = H@W2_0 + b2 -> d_out ; y2 = H@W2_1 ----------------
__global__ __launch_bounds__(320) void k_gemm2(const float* __restrict__ W20,
                                               const float* __restrict__ W21,
                                               const float* __restrict__ b2,
                                               float* __restrict__ out) {
    __shared__ float hs[64][FH];
    __shared__ float ws[FH][N2];
    const int t  = threadIdx.x;
    const int r0 = blockIdx.x * 64;

    for (int idx = t; idx < FH * N2; idx += 320) {
        int k = idx / N2;
        int j = idx % N2;
        ws[k][j] = (j < FOUT) ? W20[k * FOUT + j] : W21[k * FOUT + (j - FOUT)];
    }
    for (int idx = t; idx < 64 * FH; idx += 320) {
        int r = idx >> 6;
        int k = idx & 63;
        int row = r0 + r;
        hs[r][k] = (row < NN) ? g_H[row * FH + k] : 0.f;
    }
    __syncthreads();

    const int cg = t % 20;
    const int rg = t / 20;
    float acc[4][4];
#pragma unroll
    for (int i = 0; i < 4; i++)
#pragma unroll
        for (int j = 0; j < 4; j++) acc[i][j] = 0.f;

#pragma unroll 4
    for (int k = 0; k < FH; k++) {
        float4 w = *(const float4*)&ws[k][cg * 4];
#pragma unroll
        for (int i = 0; i < 4; i++) {
            float a = hs[rg * 4 + i][k];
            acc[i][0] += a * w.x; acc[i][1] += a * w.y;
            acc[i][2] += a * w.z; acc[i][3] += a * w.w;
        }
    }

    const int col = cg * 4;
#pragma unroll
    for (int i = 0; i < 4; i++) {
        int row = r0 + rg * 4 + i;
        if (row >= NN) continue;
        if (col < FOUT) {
            float4 bb = *(const float4*)&b2[col];
            float4 v = make_float4(acc[i][0] + bb.x, acc[i][1] + bb.y,
                                   acc[i][2] + bb.z, acc[i][3] + bb.w);
            *(float4*)&out[row * FOUT + col] = v;
        } else {
            float4 v = make_float4(acc[i][0], acc[i][1], acc[i][2], acc[i][3]);
            *(float4*)&g_y2[row * FOUT + (col - FOUT)] = v;
        }
    }
}

// ---------------- SpMM2 (pull, warp/node, float2 + 4x unroll) ------------------------
__global__ __launch_bounds__(256) void k_spmm2(float* __restrict__ out) {
    const int wid  = threadIdx.x >> 5;
    const int lane = threadIdx.x & 31;
    const int r = blockIdx.x * 8 + wid;
    if (r >= NN) return;

    const int e0 = g_off[r];
    const int d  = g_cur[r];
    const bool act = lane < 20;
    float2 a0 = {0.f, 0.f}, a1 = {0.f, 0.f}, a2 = {0.f, 0.f}, a3 = {0.f, 0.f};
    const float2* __restrict__ Y2 = (const float2*)g_y2;

    for (int base = 0; base < d; base += 32) {
        int   cl = 0;  float wl = 0.f;
        int   j  = base + lane;
        if (j < d) { cl = g_col[e0 + j]; wl = g_w[e0 + j]; }
        const int lim = min(32, d - base);
        int jj = 0;
        for (; jj + 4 <= lim; jj += 4) {
            int   c0 = __shfl_sync(0xffffffffu, cl, jj);
            int   c1 = __shfl_sync(0xffffffffu, cl, jj + 1);
            int   c2 = __shfl_sync(0xffffffffu, cl, jj + 2);
            int   c3 = __shfl_sync(0xffffffffu, cl, jj + 3);
            float w0 = __shfl_sync(0xffffffffu, wl, jj);
            float w1 = __shfl_sync(0xffffffffu, wl, jj + 1);
            float w2 = __shfl_sync(0xffffffffu, wl, jj + 2);
            float w3 = __shfl_sync(0xffffffffu, wl, jj + 3);
            if (act) {
                float2 v0 = __ldg(&Y2[c0 * 20 + lane]);
                float2 v1 = __ldg(&Y2[c1 * 20 + lane]);
                float2 v2 = __ldg(&Y2[c2 * 20 + lane]);
                float2 v3 = __ldg(&Y2[c3 * 20 + lane]);
                a0.x += w0 * v0.x; a0.y += w0 * v0.y;
                a1.x += w1 * v1.x; a1.y += w1 * v1.y;
                a2.x += w2 * v2.x; a2.y += w2 * v2.y;
                a3.x += w3 * v3.x; a3.y += w3 * v3.y;
            }
        }
        for (; jj < lim; jj++) {
            int   c = __shfl_sync(0xffffffffu, cl, jj);
            float w = __shfl_sync(0xffffffffu, wl, jj);
            if (act) {
                float2 v = __ldg(&Y2[c * 20 + lane]);
                a0.x += w * v.x; a0.y += w * v.y;
            }
        }
    }
    if (act) {
        float2 acc = make_float2(a0.x + a1.x + a2.x + a3.x,
                                 a0.y + a1.y + a2.y + a3.y);
        float2* o = &((float2*)out)[r * 20 + lane];
        float2 cur = *o;
        cur.x += acc.x; cur.y += acc.y;
        *o = cur;
    }
}

extern "C" void kernel_launch(void* const* d_in, const int* in_sizes, int n_in,
                              void* d_out, int out_size) {
    const float* x   = (const float*)d_in[0];
    const void*  ei  = d_in[1];
    const float* W10 = (const float*)d_in[2];
    const float* W11 = (const float*)d_in[3];
    const float* b1  = (const float*)d_in[4];
    const float* W20 = (const float*)d_in[5];
    const float* W21 = (const float*)d_in[6];
    const float* b2  = (const float*)d_in[7];
    float* out = (float*)d_out;

    k_zero  <<<(NN + 255) / 256, 256>>>(ei);
    k_deg   <<<(NE + 255) / 256, 256>>>(ei);
    k_scanA <<<NBLK_SCAN, SCAN_B>>>();
    k_scanC <<<NBLK_SCAN, SCAN_B>>>();
    k_bucket<<<(NE + 255) / 256, 256>>>(ei);
    k_gemm1 <<<(NN + 63) / 64, 256>>>(x, W10, W11, b1);
    k_spmm1 <<<(NN + 7) / 8, 256>>>();
    k_gemm2 <<<(NN + 63) / 64, 320>>>(W20, W21, b2, out);
    k_spmm2 <<<(NN + 7) / 8, 256>>>(out);
}

// round 9
// speedup vs baseline: 1.2094x; 1.0934x over previous
#include <cuda_runtime.h>
#include <cstdint>

#define NN   50000
#define NE   800000
#define FIN  96
#define FH   64
#define FOUT 40
#define N1   128   // FH*2
#define N2   80    // FOUT*2
#define SCAN_B 1024
#define NBLK_SCAN ((NN + SCAN_B - 1) / SCAN_B)   // 49

__device__ __align__(16) float g_C1[NN * N1];   // [h_pre | y1]
__device__ __align__(16) float g_H[NN * FH];    // relu(h_pre + A_norm y1)
__device__ __align__(16) float g_y2[NN * FOUT]; // h @ W2_1
__device__ float g_dis[NN];
__device__ int   g_deg[NN];
__device__ int   g_off[NN];
__device__ int   g_cur[NN];
__device__ int   g_bsum[NBLK_SCAN];
__device__ int   g_col[NE];
__device__ float g_w[NE];
__device__ int   g_is64;

__device__ __forceinline__ int edge_at(const void* ei, int which, int e) {
    if (g_is64) return (int)((const long long*)ei)[(size_t)which * NE + e];
    return ((const int*)ei)[(size_t)which * NE + e];
}

// tf32 conversion: destination is b32 register (bit pattern of tf32 value)
__device__ __forceinline__ float to_tf32(float x) {
    uint32_t y;
    asm("cvt.rna.tf32.f32 %0, %1;" : "=r"(y) : "f"(x));
    return __uint_as_float(y);
}

__device__ __forceinline__ void mma_tf32(float c[4], const uint32_t a[4], const uint32_t b[2]) {
    asm volatile(
        "mma.sync.aligned.m16n8k8.row.col.f32.tf32.tf32.f32 "
        "{%0,%1,%2,%3}, {%4,%5,%6,%7}, {%8,%9}, {%0,%1,%2,%3};"
        : "+f"(c[0]), "+f"(c[1]), "+f"(c[2]), "+f"(c[3])
        : "r"(a[0]), "r"(a[1]), "r"(a[2]), "r"(a[3]), "r"(b[0]), "r"(b[1]));
}

// ---------------- init (zero counters) + parallel dtype detect ----------------
__global__ void k_zero(const void* ei) {
    int i = blockIdx.x * blockDim.x + threadIdx.x;
    if (i < NN) { g_deg[i] = 0; g_cur[i] = 0; }
    if (blockIdx.x == 0 && threadIdx.x < 32) {
        const unsigned long long* p = (const unsigned long long*)ei;
        unsigned long long v0 = p[threadIdx.x];
        unsigned long long v1 = p[32 + threadIdx.x];
        int bad = (v0 >= (unsigned long long)NN) || (v1 >= (unsigned long long)NN);
        unsigned m = __ballot_sync(0xffffffffu, bad);
        if (threadIdx.x == 0) g_is64 = (m == 0u) ? 1 : 0;
    }
}

__global__ void k_deg(const void* __restrict__ ei) {
    int e = blockIdx.x * blockDim.x + threadIdx.x;
    if (e < NE) {
        int r = edge_at(ei, 0, e);
        if ((unsigned)r < NN) atomicAdd(&g_deg[r], 1);
    }
}

// ---------------- scanA (+ dis fused) ----------------
__global__ __launch_bounds__(SCAN_B) void k_scanA() {
    __shared__ int s[SCAN_B];
    int i = blockIdx.x * SCAN_B + threadIdx.x;
    int v = (i < NN) ? g_deg[i] : 0;
    if (i < NN) g_dis[i] = (v > 0) ? rsqrtf((float)v) : 0.f;
    s[threadIdx.x] = v;
    __syncthreads();
#pragma unroll
    for (int off = 1; off < SCAN_B; off <<= 1) {
        int t = (threadIdx.x >= off) ? s[threadIdx.x - off] : 0;
        __syncthreads();
        s[threadIdx.x] += t;
        __syncthreads();
    }
    if (i < NN) g_off[i] = s[threadIdx.x] - v;   // exclusive within block
    if (threadIdx.x == SCAN_B - 1) g_bsum[blockIdx.x] = s[SCAN_B - 1];
}

// scanC: add prefix of earlier block totals (per-block warp reduction)
__global__ __launch_bounds__(SCAN_B) void k_scanC() {
    __shared__ int sbase;
    const int bid = blockIdx.x;
    if (threadIdx.x < 32) {
        int lane = threadIdx.x;
        int v = (lane < bid) ? g_bsum[lane] : 0;
        if (32 + lane < bid) v += g_bsum[32 + lane];
#pragma unroll
        for (int o = 16; o > 0; o >>= 1) v += __shfl_down_sync(0xffffffffu, v, o);
        if (lane == 0) sbase = v;
    }
    __syncthreads();
    int i = bid * SCAN_B + threadIdx.x;
    if (i < NN) g_off[i] += sbase;
}

// ---------------- bucket edges into CSR ----------------
__global__ void k_bucket(const void* __restrict__ ei) {
    int e = blockIdx.x * blockDim.x + threadIdx.x;
    if (e >= NE) return;
    int r = edge_at(ei, 0, e);
    int c = edge_at(ei, 1, e);
    if ((unsigned)r >= NN || (unsigned)c >= NN) return;
    int slot = g_off[r] + atomicAdd(&g_cur[r], 1);
    g_col[slot] = c;
    g_w[slot]   = -g_dis[r] * g_dis[c];
}

// ---------------- GEMM1 (tf32): C1 = x @ [W1_0|W1_1] (+b1 on cols<64) ----------------
__global__ __launch_bounds__(256) void k_gemm1(const float* __restrict__ x,
                                               const float* __restrict__ W0,
                                               const float* __restrict__ W1,
                                               const float* __restrict__ b1) {
    __shared__ float xs[64][36];
    __shared__ float ws[32][136];
    const int t    = threadIdx.x;
    const int lane = t & 31;
    const int w    = t >> 5;
    const int wr   = w >> 2;        // 0..1
    const int wc   = w & 3;         // 0..3
    const int r0   = blockIdx.x * 64;

    float acc[2][4][4];
#pragma unroll
    for (int mb = 0; mb < 2; mb++)
#pragma unroll
        for (int nb = 0; nb < 4; nb++)
#pragma unroll
            for (int q = 0; q < 4; q++) acc[mb][nb][q] = 0.f;

    for (int kc = 0; kc < FIN; kc += 32) {
        for (int idx = t; idx < 512; idx += 256) {
            int r  = idx >> 3;
            int c4 = idx & 7;
            int row = r0 + r;
            float4 v = make_float4(0.f, 0.f, 0.f, 0.f);
            if (row < NN) v = *(const float4*)&x[row * FIN + kc + c4 * 4];
            xs[r][c4 * 4 + 0] = to_tf32(v.x);
            xs[r][c4 * 4 + 1] = to_tf32(v.y);
            xs[r][c4 * 4 + 2] = to_tf32(v.z);
            xs[r][c4 * 4 + 3] = to_tf32(v.w);
        }
        for (int idx = t; idx < 32 * FH; idx += 256) {
            int kk = idx >> 6;
            int j  = idx & 63;
            int gk = kc + kk;
            ws[kk][j]      = to_tf32(W0[gk * FH + j]);
            ws[kk][64 + j] = to_tf32(W1[gk * FH + j]);
        }
        __syncthreads();

#pragma unroll
        for (int kk = 0; kk < 32; kk += 8) {
            uint32_t a[2][4];
            const int ar = lane >> 2;
            const int ak = kk + (lane & 3);
#pragma unroll
            for (int mb = 0; mb < 2; mb++) {
                int rr = wr * 32 + mb * 16 + ar;
                a[mb][0] = __float_as_uint(xs[rr][ak]);
                a[mb][1] = __float_as_uint(xs[rr + 8][ak]);
                a[mb][2] = __float_as_uint(xs[rr][ak + 4]);
                a[mb][3] = __float_as_uint(xs[rr + 8][ak + 4]);
            }
#pragma unroll
            for (int nb = 0; nb < 4; nb++) {
                uint32_t b[2];
                int col = wc * 32 + nb * 8 + (lane >> 2);
                b[0] = __float_as_uint(ws[ak][col]);
                b[1] = __float_as_uint(ws[ak + 4][col]);
                mma_tf32(acc[0][nb], a[0], b);
                mma_tf32(acc[1][nb], a[1], b);
            }
        }
        __syncthreads();
    }

#pragma unroll
    for (int mb = 0; mb < 2; mb++) {
#pragma unroll
        for (int nb = 0; nb < 4; nb++) {
            int row = r0 + wr * 32 + mb * 16 + (lane >> 2);
            int col = wc * 32 + nb * 8 + (lane & 3) * 2;
            float bx = 0.f, by = 0.f;
            if (col < FH) { bx = b1[col]; by = b1[col + 1]; }
            if (row < NN) {
                float2 v0 = make_float2(acc[mb][nb][0] + bx, acc[mb][nb][1] + by);
                *(float2*)&g_C1[row * N1 + col] = v0;
            }
            if (row + 8 < NN) {
                float2 v1 = make_float2(acc[mb][nb][2] + bx, acc[mb][nb][3] + by);
                *(float2*)&g_C1[(row + 8) * N1 + col] = v1;
            }
        }
    }
}

// ---------------- SpMM1 (pull, warp/node, float2 + 4x unroll) ------------------------
__global__ __launch_bounds__(256) void k_spmm1() {
    const int wid  = threadIdx.x >> 5;
    const int lane = threadIdx.x & 31;
    const int r = blockIdx.x * 8 + wid;
    if (r >= NN) return;

    const int e0 = g_off[r];
    const int d  = g_cur[r];
    float2 a0 = {0.f, 0.f}, a1 = {0.f, 0.f}, a2 = {0.f, 0.f}, a3 = {0.f, 0.f};
    const float2* __restrict__ C2 = (const float2*)g_C1;

    for (int base = 0; base < d; base += 32) {
        int   cl = 0;  float wl = 0.f;
        int   j  = base + lane;
        if (j < d) { cl = g_col[e0 + j]; wl = g_w[e0 + j]; }
        const int lim = min(32, d - base);
        int jj = 0;
        for (; jj + 4 <= lim; jj += 4) {
            int   c0 = __shfl_sync(0xffffffffu, cl, jj);
            int   c1 = __shfl_sync(0xffffffffu, cl, jj + 1);
            int   c2 = __shfl_sync(0xffffffffu, cl, jj + 2);
            int   c3 = __shfl_sync(0xffffffffu, cl, jj + 3);
            float w0 = __shfl_sync(0xffffffffu, wl, jj);
            float w1 = __shfl_sync(0xffffffffu, wl, jj + 1);
            float w2 = __shfl_sync(0xffffffffu, wl, jj + 2);
            float w3 = __shfl_sync(0xffffffffu, wl, jj + 3);
            float2 v0 = __ldg(&C2[c0 * 64 + 32 + lane]);
            float2 v1 = __ldg(&C2[c1 * 64 + 32 + lane]);
            float2 v2 = __ldg(&C2[c2 * 64 + 32 + lane]);
            float2 v3 = __ldg(&C2[c3 * 64 + 32 + lane]);
            a0.x += w0 * v0.x; a0.y += w0 * v0.y;
            a1.x += w1 * v1.x; a1.y += w1 * v1.y;
            a2.x += w2 * v2.x; a2.y += w2 * v2.y;
            a3.x += w3 * v3.x; a3.y += w3 * v3.y;
        }
        for (; jj < lim; jj++) {
            int   c = __shfl_sync(0xffffffffu, cl, jj);
            float w = __shfl_sync(0xffffffffu, wl, jj);
            float2 v = __ldg(&C2[c * 64 + 32 + lane]);
            a0.x += w * v.x; a0.y += w * v.y;
        }
    }
    float2 acc = make_float2(a0.x + a1.x + a2.x + a3.x,
                             a0.y + a1.y + a2.y + a3.y);
    float2 pre = C2[r * 64 + lane];
    float2 hv = make_float2(fmaxf(pre.x + acc.x, 0.f), fmaxf(pre.y + acc.y, 0.f));
    ((float2*)g_H)[r * 32 + lane] = hv;
}

// ---------------- GEMM2 (tf32): out = H@W2_0 + b2 -> d_out ; y2 = H@W2_1 -------------
// CTA: 128 thr = 4 warps. CTA tile 64x80, warp tile 16x80, K=64 in one smem stage.
__global__ __launch_bounds__(128) void k_gemm2(const float* __restrict__ W20,
                                               const float* __restrict__ W21,
                                               const float* __restrict__ b2,
                                               float* __restrict__ out) {
    __shared__ float hs[64][68];    // 64 rows x 64 k, stride 68 (conflict-free A frags)
    __shared__ float ws[64][88];    // 64 k x 80 cols, stride 88 (conflict-free B frags)
    const int t    = threadIdx.x;
    const int lane = t & 31;
    const int w    = t >> 5;        // 0..3 -> rows w*16..w*16+15
    const int r0   = blockIdx.x * 64;

    // stage H tile (tf32)
    for (int idx = t; idx < 64 * FH; idx += 128) {
        int r = idx >> 6;
        int k = idx & 63;
        int row = r0 + r;
        hs[r][k] = (row < NN) ? to_tf32(g_H[row * FH + k]) : 0.f;
    }
    // stage [W2_0 | W2_1] (tf32)
    for (int idx = t; idx < FH * N2; idx += 128) {
        int k = idx / N2;
        int j = idx % N2;
        float v = (j < FOUT) ? W20[k * FOUT + j] : W21[k * FOUT + (j - FOUT)];
        ws[k][j] = to_tf32(v);
    }
    __syncthreads();

    float acc[10][4];
#pragma unroll
    for (int nb = 0; nb < 10; nb++)
#pragma unroll
        for (int q = 0; q < 4; q++) acc[nb][q] = 0.f;

#pragma unroll
    for (int kk = 0; kk < FH; kk += 8) {
        const int ar = lane >> 2;
        const int ak = kk + (lane & 3);
        uint32_t a[4];
        int rr = w * 16 + ar;
        a[0] = __float_as_uint(hs[rr][ak]);
        a[1] = __float_as_uint(hs[rr + 8][ak]);
        a[2] = __float_as_uint(hs[rr][ak + 4]);
        a[3] = __float_as_uint(hs[rr + 8][ak + 4]);
#pragma unroll
        for (int nb = 0; nb < 10; nb++) {
            uint32_t b[2];
            int col = nb * 8 + (lane >> 2);
            b[0] = __float_as_uint(ws[ak][col]);
            b[1] = __float_as_uint(ws[ak + 4][col]);
            mma_tf32(acc[nb], a, b);
        }
    }

#pragma unroll
    for (int nb = 0; nb < 10; nb++) {
        int row = r0 + w * 16 + (lane >> 2);
        int col = nb * 8 + (lane & 3) * 2;
        if (col < FOUT) {
            float bx = b2[col], by = b2[col + 1];
            if (row < NN)
                *(float2*)&out[row * FOUT + col] =
                    make_float2(acc[nb][0] + bx, acc[nb][1] + by);
            if (row + 8 < NN)
                *(float2*)&out[(row + 8) * FOUT + col] =
                    make_float2(acc[nb][2] + bx, acc[nb][3] + by);
        } else {
            int c2 = col - FOUT;
            if (row < NN)
                *(float2*)&g_y2[row * FOUT + c2] = make_float2(acc[nb][0], acc[nb][1]);
            if (row + 8 < NN)
                *(float2*)&g_y2[(row + 8) * FOUT + c2] = make_float2(acc[nb][2], acc[nb][3]);
        }
    }
}

// ---------------- SpMM2 (pull, warp/node, float2 + 4x unroll) ------------------------
__global__ __launch_bounds__(256) void k_spmm2(float* __restrict__ out) {
    const int wid  = threadIdx.x >> 5;
    const int lane = threadIdx.x & 31;
    const int r = blockIdx.x * 8 + wid;
    if (r >= NN) return;

    const int e0 = g_off[r];
    const int d  = g_cur[r];
    const bool act = lane < 20;
    float2 a0 = {0.f, 0.f}, a1 = {0.f, 0.f}, a2 = {0.f, 0.f}, a3 = {0.f, 0.f};
    const float2* __restrict__ Y2 = (const float2*)g_y2;

    for (int base = 0; base < d; base += 32) {
        int   cl = 0;  float wl = 0.f;
        int   j  = base + lane;
        if (j < d) { cl = g_col[e0 + j]; wl = g_w[e0 + j]; }
        const int lim = min(32, d - base);
        int jj = 0;
        for (; jj + 4 <= lim; jj += 4) {
            int   c0 = __shfl_sync(0xffffffffu, cl, jj);
            int   c1 = __shfl_sync(0xffffffffu, cl, jj + 1);
            int   c2 = __shfl_sync(0xffffffffu, cl, jj + 2);
            int   c3 = __shfl_sync(0xffffffffu, cl, jj + 3);
            float w0 = __shfl_sync(0xffffffffu, wl, jj);
            float w1 = __shfl_sync(0xffffffffu, wl, jj + 1);
            float w2 = __shfl_sync(0xffffffffu, wl, jj + 2);
            float w3 = __shfl_sync(0xffffffffu, wl, jj + 3);
            if (act) {
                float2 v0 = __ldg(&Y2[c0 * 20 + lane]);
                float2 v1 = __ldg(&Y2[c1 * 20 + lane]);
                float2 v2 = __ldg(&Y2[c2 * 20 + lane]);
                float2 v3 = __ldg(&Y2[c3 * 20 + lane]);
                a0.x += w0 * v0.x; a0.y += w0 * v0.y;
                a1.x += w1 * v1.x; a1.y += w1 * v1.y;
                a2.x += w2 * v2.x; a2.y += w2 * v2.y;
                a3.x += w3 * v3.x; a3.y += w3 * v3.y;
            }
        }
        for (; jj < lim; jj++) {
            int   c = __shfl_sync(0xffffffffu, cl, jj);
            float w = __shfl_sync(0xffffffffu, wl, jj);
            if (act) {
                float2 v = __ldg(&Y2[c * 20 + lane]);
                a0.x += w * v.x; a0.y += w * v.y;
            }
        }
    }
    if (act) {
        float2 acc = make_float2(a0.x + a1.x + a2.x + a3.x,
                                 a0.y + a1.y + a2.y + a3.y);
        float2* o = &((float2*)out)[r * 20 + lane];
        float2 cur = *o;
        cur.x += acc.x; cur.y += acc.y;
        *o = cur;
    }
}

extern "C" void kernel_launch(void* const* d_in, const int* in_sizes, int n_in,
                              void* d_out, int out_size) {
    const float* x   = (const float*)d_in[0];
    const void*  ei  = d_in[1];
    const float* W10 = (const float*)d_in[2];
    const float* W11 = (const float*)d_in[3];
    const float* b1  = (const float*)d_in[4];
    const float* W20 = (const float*)d_in[5];
    const float* W21 = (const float*)d_in[6];
    const float* b2  = (const float*)d_in[7];
    float* out = (float*)d_out;

    k_zero  <<<(NN + 255) / 256, 256>>>(ei);
    k_deg   <<<(NE + 255) / 256, 256>>>(ei);
    k_scanA <<<NBLK_SCAN, SCAN_B>>>();
    k_scanC <<<NBLK_SCAN, SCAN_B>>>();
    k_bucket<<<(NE + 255) / 256, 256>>>(ei);
    k_gemm1 <<<(NN + 63) / 64, 256>>>(x, W10, W11, b1);
    k_spmm1 <<<(NN + 7) / 8, 256>>>();
    k_gemm2 <<<(NN + 63) / 64, 128>>>(W20, W21, b2, out);
    k_spmm2 <<<(NN + 7) / 8, 256>>>(out);
}